// round 11
// baseline (speedup 1.0000x reference)
#include <cuda_runtime.h>
#include <cuda_bf16.h>
#include <cstdint>

// Problem constants
#define B_  64
#define S_  2048
#define E_  256
#define H_  256

#define NCONS 64          // consumer CTAs (one per batch)
#define NPROD 48          // producer CTAs
#define NCTAS (NCONS + NPROD)

// Scratch (device-global: runtime allocation is forbidden)
__device__ float g_xw[(size_t)B_ * S_ * H_];   // 128 MB: xw[b,s,h]
__device__ float g_UwT[H_ * H_];               // UwT[k][h] = Uw[h][k]
__device__ float g_WwT[E_ * H_];               // WwT[e][h] = Ww[h][e]
__device__ int   g_flag[S_];                   // per-timestep ready flags

__device__ __forceinline__ int ld_acquire_gpu(const int* p) {
    int v;
    asm volatile("ld.acquire.gpu.global.b32 %0, [%1];" : "=r"(v) : "l"(p) : "memory");
    return v;
}
__device__ __forceinline__ void st_release_gpu(int* p, int v) {
    asm volatile("st.release.gpu.global.b32 [%0], %1;" :: "l"(p), "r"(v) : "memory");
}
__device__ __forceinline__ float ld_cg_f(const float* p) {
    float v;
    asm volatile("ld.global.cg.f32 %0, [%1];" : "=f"(v) : "l"(p) : "memory");
    return v;
}

// Fast tanh: 1 - 2/(e^{2x}+1). |err| ~1e-6; exact saturation at +/-inf.
__device__ __forceinline__ float fast_tanh(float x) {
    float e = __expf(2.0f * x);
    float r;
    asm("rcp.approx.f32 %0, %1;" : "=f"(r) : "f"(e + 1.0f));
    return fmaf(-2.0f, r, 1.0f);
}

// ---------------------------------------------------------------------------
// prep: transpose Uw and Ww, zero flags
// ---------------------------------------------------------------------------
__global__ void prep(const float* __restrict__ Uw, const float* __restrict__ Ww) {
    int k = blockIdx.x;
    int h = threadIdx.x;
    g_UwT[k * H_ + h] = Uw[h * H_ + k];
    g_WwT[k * H_ + h] = Ww[h * E_ + k];
    if (k < 8) g_flag[k * H_ + h] = 0;   // 8*256 = 2048 flags
}

// ---------------------------------------------------------------------------
// Fused persistent kernel: 64 consumers + 48 producers, all co-resident.
// ---------------------------------------------------------------------------
#define UREG 208                       // register-resident u rows (was 192)
#define USM  (H_ - UREG)               // 48 rows in smem as float2 pairs
#define NVQ  (UREG / 4)                // 52 v-quad groups in register phase

#define SCAN_SMEM_FLOATS (USM * H_ + 2 * H_)
#define SMEM_BYTES (SCAN_SMEM_FLOATS * 4)

#define PK 16
#define APAD 4
#define BPAD 4

__global__ __launch_bounds__(256, 1)
void fused(const float* __restrict__ x,       // [B,S,E]
           const float* __restrict__ Wb,      // [H]
           const float* __restrict__ Ub,      // [H]
           float* __restrict__ Out,           // [B,S,H]
           float* __restrict__ Tfin) {        // [B,H]
    extern __shared__ float sm[];
    const int tid = threadIdx.x;

    if (blockIdx.x >= NCONS) {
        // ================= PRODUCER: one 64x256x256 GEMM per timestep =====
        const int p  = blockIdx.x - NCONS;
        float* As = sm;                                   // [PK][64+APAD]
        float* Bs = sm + PK * (64 + APAD);                // [PK][256+BPAD]
        const int ASTR = 64 + APAD;
        const int BSTR = H_ + BPAD;

        const int tx = tid & 15;                           // h quad group
        const int ty = tid >> 4;                           // b quad group
        const int arow = tid >> 2, akq = tid & 3;          // A-tile loads
        const int bk = tid >> 4, bh0 = (tid & 15) * 16;    // B-tile loads

        float4 bias[4];
        #pragma unroll
        for (int q = 0; q < 4; q++)
            bias[q] = *(const float4*)&Wb[tx * 4 + 64 * q];

        for (int s = p; s < S_; s += NPROD) {
            float acc[4][16] = {};

            const float* xs = x + (size_t)s * E_;
            float4 ra  = *(const float4*)&xs[(size_t)arow * S_ * E_ + akq * 4];
            float4 rb0 = *(const float4*)&g_WwT[bk * H_ + bh0 + 0];
            float4 rb1 = *(const float4*)&g_WwT[bk * H_ + bh0 + 4];
            float4 rb2 = *(const float4*)&g_WwT[bk * H_ + bh0 + 8];
            float4 rb3 = *(const float4*)&g_WwT[bk * H_ + bh0 + 12];

            for (int k0 = 0; k0 < E_; k0 += PK) {
                As[(akq * 4 + 0) * ASTR + arow] = ra.x;
                As[(akq * 4 + 1) * ASTR + arow] = ra.y;
                As[(akq * 4 + 2) * ASTR + arow] = ra.z;
                As[(akq * 4 + 3) * ASTR + arow] = ra.w;
                *(float4*)&Bs[bk * BSTR + bh0 + 0]  = rb0;
                *(float4*)&Bs[bk * BSTR + bh0 + 4]  = rb1;
                *(float4*)&Bs[bk * BSTR + bh0 + 8]  = rb2;
                *(float4*)&Bs[bk * BSTR + bh0 + 12] = rb3;
                __syncthreads();

                if (k0 + PK < E_) {
                    const int kn = k0 + PK;
                    ra  = *(const float4*)&xs[(size_t)arow * S_ * E_ + kn + akq * 4];
                    rb0 = *(const float4*)&g_WwT[(kn + bk) * H_ + bh0 + 0];
                    rb1 = *(const float4*)&g_WwT[(kn + bk) * H_ + bh0 + 4];
                    rb2 = *(const float4*)&g_WwT[(kn + bk) * H_ + bh0 + 8];
                    rb3 = *(const float4*)&g_WwT[(kn + bk) * H_ + bh0 + 12];
                }

                #pragma unroll
                for (int k = 0; k < PK; k++) {
                    float4 a  = *(const float4*)&As[k * ASTR + ty * 4];
                    float4 b0 = *(const float4*)&Bs[k * BSTR + tx * 4 + 0];
                    float4 b1 = *(const float4*)&Bs[k * BSTR + tx * 4 + 64];
                    float4 b2 = *(const float4*)&Bs[k * BSTR + tx * 4 + 128];
                    float4 b3 = *(const float4*)&Bs[k * BSTR + tx * 4 + 192];
                    float av;
                    #pragma unroll
                    for (int r = 0; r < 4; r++) {
                        av = (r == 0) ? a.x : (r == 1) ? a.y : (r == 2) ? a.z : a.w;
                        acc[r][0]  += av * b0.x; acc[r][1]  += av * b0.y;
                        acc[r][2]  += av * b0.z; acc[r][3]  += av * b0.w;
                        acc[r][4]  += av * b1.x; acc[r][5]  += av * b1.y;
                        acc[r][6]  += av * b1.z; acc[r][7]  += av * b1.w;
                        acc[r][8]  += av * b2.x; acc[r][9]  += av * b2.y;
                        acc[r][10] += av * b2.z; acc[r][11] += av * b2.w;
                        acc[r][12] += av * b3.x; acc[r][13] += av * b3.y;
                        acc[r][14] += av * b3.z; acc[r][15] += av * b3.w;
                    }
                }
                __syncthreads();
            }

            #pragma unroll
            for (int r = 0; r < 4; r++) {
                const int b = ty * 4 + r;
                float* row = g_xw + ((size_t)b * S_ + s) * H_;
                #pragma unroll
                for (int q = 0; q < 4; q++) {
                    float4 o = make_float4(acc[r][q * 4 + 0] + bias[q].x,
                                           acc[r][q * 4 + 1] + bias[q].y,
                                           acc[r][q * 4 + 2] + bias[q].z,
                                           acc[r][q * 4 + 3] + bias[q].w);
                    *(float4*)&row[tx * 4 + 64 * q] = o;
                }
            }
            __syncthreads();
            if (tid == 0) {
                __threadfence();
                st_release_gpu(&g_flag[s], 1);
            }
        }
        return;
    }

    // ================= CONSUMER (per-batch recurrence) =====================
    float2* u2  = (float2*)sm;
    float*  vsm = sm + (size_t)USM * H_;

    const int b = blockIdx.x;

    float uw[UREG];
    #pragma unroll
    for (int j = 0; j < UREG; j++)
        uw[j] = g_UwT[j * H_ + tid];

    for (int r2 = 0; r2 < USM / 2; r2++) {
        float a = g_UwT[(UREG + 2 * r2 + 0) * H_ + tid];
        float c = g_UwT[(UREG + 2 * r2 + 1) * H_ + tid];
        u2[r2 * H_ + tid] = make_float2(a, c);
    }
    __syncthreads();

    const float ub = Ub[tid];
    float t = 0.0f;

    const float* xwp = g_xw + (size_t)b * S_ * H_ + tid;
    float*       op  = Out  + (size_t)b * S_ * H_ + tid;

    while (ld_acquire_gpu(&g_flag[0]) == 0) { }
    float xv = __ldcs(xwp);

    for (int s = 0; s < S_; s++) {
        float v = fast_tanh(xv + t);
        float* vb = vsm + (s & 1) * H_;
        vb[tid] = v;
        __syncthreads();

        // Speculative next-step fetch: acquire flag + load xw; validate AFTER
        // the long dot so neither latency is exposed.
        int   fspec = 1;
        float xn    = 0.0f;
        const float* xnp = xwp + (size_t)(s + 1) * H_;
        if (s + 1 < S_) {
            fspec = ld_acquire_gpu(&g_flag[s + 1]);
            xn    = __ldcs(xnp);
        }

        const float4* v4 = (const float4*)vb;
        float a0 = ub, a1 = 0.f, a2 = 0.f, a3 = 0.f;
        float a4 = 0.f, a5 = 0.f, a6 = 0.f, a7 = 0.f;

        float4 vA = v4[0];
        float4 vB = v4[1];

        // Register section: rows [0,208) = 52 float4 groups, 2-deep v pipe
        #pragma unroll
        for (int q = 0; q < NVQ; q += 2) {
            float4 nA, nB;
            if (q + 2 < NVQ + 2) { nA = v4[q + 2]; nB = v4[q + 3]; }
            const int j = 4 * q;
            a0 += uw[j + 0] * vA.x;  a1 += uw[j + 1] * vA.y;
            a2 += uw[j + 2] * vA.z;  a3 += uw[j + 3] * vA.w;
            a4 += uw[j + 4] * vB.x;  a5 += uw[j + 5] * vB.y;
            a6 += uw[j + 6] * vB.z;  a7 += uw[j + 7] * vB.w;
            vA = nA; vB = nB;
        }

        // Shared-memory section: rows [208,256) = 12 float4 groups
        const float2* up = u2 + tid;
        #pragma unroll
        for (int q = NVQ; q < 64; q += 2) {
            float4 nA, nB;
            if (q + 2 < 64) { nA = v4[q + 2]; nB = v4[q + 3]; }
            else            { nA = vA;        nB = vB;        }
            const int r2b = (4 * q - UREG) >> 1;
            float2 u0 = up[(r2b + 0) * H_];
            float2 u1 = up[(r2b + 1) * H_];
            float2 uu = up[(r2b + 2) * H_];
            float2 u3 = up[(r2b + 3) * H_];
            a0 += u0.x * vA.x;  a1 += u0.y * vA.y;
            a2 += u1.x * vA.z;  a3 += u1.y * vA.w;
            a4 += uu.x * vB.x;  a5 += uu.y * vB.y;
            a6 += u3.x * vB.z;  a7 += u3.y * vB.w;
            vA = nA; vB = nB;
        }

        t = ((a0 + a1) + (a2 + a3)) + ((a4 + a5) + (a6 + a7));
        __stcs(&op[(size_t)s * H_], t);

        // Validate speculation (slow path only during producer ramp)
        if (s + 1 < S_) {
            if (fspec == 0) {
                while (ld_acquire_gpu(&g_flag[s + 1]) == 0) { }
                xn = ld_cg_f(xnp);
            }
            xv = xn;
        }
    }

    Tfin[b * H_ + tid] = t;
}

// ---------------------------------------------------------------------------
// Launcher
// ---------------------------------------------------------------------------
extern "C" void kernel_launch(void* const* d_in, const int* in_sizes, int n_in,
                              void* d_out, int out_size) {
    const float* x  = (const float*)d_in[0];   // [B,S,E]
    const float* Ww = (const float*)d_in[1];   // [H,E]
    const float* Wb = (const float*)d_in[2];   // [H]
    const float* Uw = (const float*)d_in[3];   // [H,H]
    const float* Ub = (const float*)d_in[4];   // [H]

    float* out  = (float*)d_out;
    float* tfin = out;                          // [B,H]
    float* O    = out + (size_t)B_ * H_;        // [B,S,H]

    cudaFuncSetAttribute(fused, cudaFuncAttributeMaxDynamicSharedMemorySize,
                         SMEM_BYTES);

    prep<<<H_, H_>>>(Uw, Ww);
    fused<<<NCTAS, 256, SMEM_BYTES>>>(x, Wb, Ub, O, tfin);
}

// round 13
// speedup vs baseline: 1.1957x; 1.1957x over previous
#include <cuda_runtime.h>
#include <cuda_bf16.h>
#include <cstdint>

// Problem constants
#define B_  64
#define S_  2048
#define E_  256
#define H_  256
#define M_TOT (B_ * S_)        // 131072 rows

// Scratch (device-global: runtime allocation is forbidden)
__device__ float         g_xw [(size_t)M_TOT * H_];   // 128 MB
__device__ __nv_bfloat16 g_xhi[(size_t)M_TOT * E_];   // 64 MB
__device__ __nv_bfloat16 g_xlo[(size_t)M_TOT * E_];   // 64 MB
__device__ __nv_bfloat16 g_Whi[H_ * E_];
__device__ __nv_bfloat16 g_Wlo[H_ * E_];
__device__ float         g_UwT[H_ * H_];              // UwT[k][h] = Uw[h][k]

// Fast tanh: 1 - 2/(e^{2x}+1). |err| ~1e-6; exact saturation at +/-inf.
__device__ __forceinline__ float fast_tanh(float x) {
    float e = __expf(2.0f * x);
    float r;
    asm("rcp.approx.f32 %0, %1;" : "=f"(r) : "f"(e + 1.0f));
    return fmaf(-2.0f, r, 1.0f);
}

// ---------------------------------------------------------------------------
// prep kernels
// ---------------------------------------------------------------------------
__global__ void prep_uwt(const float* __restrict__ Uw) {
    int k = blockIdx.x, h = threadIdx.x;
    g_UwT[k * H_ + h] = Uw[h * H_ + k];
}

__global__ void prep_wsplit(const float* __restrict__ Ww) {
    int i = blockIdx.x * 256 + threadIdx.x;     // 256 blocks x 256 thr = 65536
    float v = Ww[i];
    __nv_bfloat16 hb = __float2bfloat16_rn(v);
    g_Whi[i] = hb;
    g_Wlo[i] = __float2bfloat16_rn(v - __bfloat162float(hb));
}

__global__ void prep_xsplit(const float* __restrict__ x) {
    size_t i4 = (size_t)blockIdx.x * blockDim.x + threadIdx.x;
    const size_t n4 = (size_t)M_TOT * E_ / 4;
    for (; i4 < n4; i4 += (size_t)gridDim.x * blockDim.x) {
        float4 v = ((const float4*)x)[i4];
        __nv_bfloat16 h0 = __float2bfloat16_rn(v.x);
        __nv_bfloat16 h1 = __float2bfloat16_rn(v.y);
        __nv_bfloat16 h2 = __float2bfloat16_rn(v.z);
        __nv_bfloat16 h3 = __float2bfloat16_rn(v.w);
        __nv_bfloat16 l0 = __float2bfloat16_rn(v.x - __bfloat162float(h0));
        __nv_bfloat16 l1 = __float2bfloat16_rn(v.y - __bfloat162float(h1));
        __nv_bfloat16 l2 = __float2bfloat16_rn(v.z - __bfloat162float(h2));
        __nv_bfloat16 l3 = __float2bfloat16_rn(v.w - __bfloat162float(h3));
        __nv_bfloat162* ph = (__nv_bfloat162*)&g_xhi[i4 * 4];
        __nv_bfloat162* pl = (__nv_bfloat162*)&g_xlo[i4 * 4];
        ph[0] = __nv_bfloat162(h0, h1); ph[1] = __nv_bfloat162(h2, h3);
        pl[0] = __nv_bfloat162(l0, l1); pl[1] = __nv_bfloat162(l2, l3);
    }
}

// ---------------------------------------------------------------------------
// Tensor-core GEMM: xw = x_hi*W_hi + x_lo*W_hi + x_hi*W_lo + Wb
//   CTA tile 128(M) x 64(N), 8 warps (4 M x 2 N), warp tile 32x32.
//   24 k-iterations (8 chunks x 3 segments), reg-prefetched.
//   smem stride 40 bf16 (80B) -> conflict-free ldmatrix.
//   Loads: each thread fetches TWO uint4 (16 bf16) to cover full 32-el chunk.
// ---------------------------------------------------------------------------
#define ASTRIDE 40
#define BSTRIDE 40

__device__ __forceinline__ void ldmx4(uint32_t& r0, uint32_t& r1, uint32_t& r2, uint32_t& r3,
                                      uint32_t addr) {
    asm volatile("ldmatrix.sync.aligned.m8n8.x4.shared.b16 {%0,%1,%2,%3}, [%4];"
                 : "=r"(r0), "=r"(r1), "=r"(r2), "=r"(r3) : "r"(addr));
}
__device__ __forceinline__ void mma16816(float& d0, float& d1, float& d2, float& d3,
                                         uint32_t a0, uint32_t a1, uint32_t a2, uint32_t a3,
                                         uint32_t b0, uint32_t b1) {
    asm volatile("mma.sync.aligned.m16n8k16.row.col.f32.bf16.bf16.f32 "
                 "{%0,%1,%2,%3}, {%4,%5,%6,%7}, {%8,%9}, {%0,%1,%2,%3};"
                 : "+f"(d0), "+f"(d1), "+f"(d2), "+f"(d3)
                 : "r"(a0), "r"(a1), "r"(a2), "r"(a3), "r"(b0), "r"(b1));
}

__global__ __launch_bounds__(256) void gemm_bf16(const float* __restrict__ Wb) {
    __shared__ __nv_bfloat16 As[128 * ASTRIDE];
    __shared__ __nv_bfloat16 Bs[64 * BSTRIDE];

    const int tid   = threadIdx.x;
    const int lane  = tid & 31;
    const int warp  = tid >> 5;
    const int warpM = warp >> 1;           // 0..3
    const int warpN = warp & 1;            // 0..1
    const int grp   = lane >> 2;
    const int qid   = lane & 3;

    const size_t row0 = (size_t)blockIdx.y * 128;
    const int    n0   = blockIdx.x * 64;

    // Gmem load coords: 2 threads per row, each covering 16 elements (2x uint4)
    const int arow = tid >> 1, acol = (tid & 1) * 16;      // A: 128 rows
    const int brow = tid >> 1, bcol = (tid & 1) * 16;      // B: 64 rows (tid<128)

    float d[2][4][4];
    #pragma unroll
    for (int i = 0; i < 2; i++)
        #pragma unroll
        for (int j = 0; j < 4; j++)
            #pragma unroll
            for (int c = 0; c < 4; c++) d[i][j][c] = 0.0f;

    uint32_t as_base = (uint32_t)__cvta_generic_to_shared(As);
    uint32_t bs_base = (uint32_t)__cvta_generic_to_shared(Bs);

    // prefetch iteration 0 (seg 0: xhi * Whi)
    uint4 ra0 = *(const uint4*)&g_xhi[(row0 + arow) * E_ + acol + 0];
    uint4 ra1 = *(const uint4*)&g_xhi[(row0 + arow) * E_ + acol + 8];
    uint4 rb0 = make_uint4(0, 0, 0, 0), rb1 = make_uint4(0, 0, 0, 0);
    if (tid < 128) {
        rb0 = *(const uint4*)&g_Whi[(size_t)(n0 + brow) * E_ + bcol + 0];
        rb1 = *(const uint4*)&g_Whi[(size_t)(n0 + brow) * E_ + bcol + 8];
    }

    for (int it = 0; it < 24; it++) {
        // store prefetched regs -> smem (full 32-element chunk per row)
        *(uint4*)&As[arow * ASTRIDE + acol + 0] = ra0;
        *(uint4*)&As[arow * ASTRIDE + acol + 8] = ra1;
        if (tid < 128) {
            *(uint4*)&Bs[brow * BSTRIDE + bcol + 0] = rb0;
            *(uint4*)&Bs[brow * BSTRIDE + bcol + 8] = rb1;
        }
        __syncthreads();

        // prefetch next
        if (it + 1 < 24) {
            int nit = it + 1;
            int seg = nit >> 3, kc = nit & 7;
            const __nv_bfloat16* nA = (seg == 1) ? g_xlo : g_xhi;
            const __nv_bfloat16* nB = (seg == 2) ? g_Wlo : g_Whi;
            ra0 = *(const uint4*)&nA[(row0 + arow) * E_ + kc * 32 + acol + 0];
            ra1 = *(const uint4*)&nA[(row0 + arow) * E_ + kc * 32 + acol + 8];
            if (tid < 128) {
                rb0 = *(const uint4*)&nB[(size_t)(n0 + brow) * E_ + kc * 32 + bcol + 0];
                rb1 = *(const uint4*)&nB[(size_t)(n0 + brow) * E_ + kc * 32 + bcol + 8];
            }
        }

        // compute on current smem chunk (k = 0..31)
        #pragma unroll
        for (int k16 = 0; k16 < 32; k16 += 16) {
            uint32_t a[2][4], b[2][4];
            #pragma unroll
            for (int i = 0; i < 2; i++) {
                int r = warpM * 32 + i * 16 + (lane & 15);
                int c = k16 + ((lane >> 4) << 3);
                ldmx4(a[i][0], a[i][1], a[i][2], a[i][3],
                      as_base + (uint32_t)(r * ASTRIDE + c) * 2);
            }
            #pragma unroll
            for (int j2 = 0; j2 < 2; j2++) {
                int n = warpN * 32 + j2 * 16 + (((lane >> 4) & 1) << 3) + (lane & 7);
                int c = k16 + (((lane >> 3) & 1) << 3);
                ldmx4(b[j2][0], b[j2][1], b[j2][2], b[j2][3],
                      bs_base + (uint32_t)(n * BSTRIDE + c) * 2);
            }
            #pragma unroll
            for (int i = 0; i < 2; i++)
                #pragma unroll
                for (int j = 0; j < 4; j++) {
                    int j2 = j >> 1, sel = (j & 1) * 2;
                    mma16816(d[i][j][0], d[i][j][1], d[i][j][2], d[i][j][3],
                             a[i][0], a[i][1], a[i][2], a[i][3],
                             b[j2][sel], b[j2][sel + 1]);
                }
        }
        __syncthreads();
    }

    // epilogue: add bias, store fp32
    #pragma unroll
    for (int j = 0; j < 4; j++) {
        int col = n0 + warpN * 32 + j * 8 + qid * 2;
        float2 wb = *(const float2*)&Wb[col];
        #pragma unroll
        for (int i = 0; i < 2; i++) {
            size_t r = row0 + warpM * 32 + i * 16 + grp;
            float2 o0 = make_float2(d[i][j][0] + wb.x, d[i][j][1] + wb.y);
            float2 o1 = make_float2(d[i][j][2] + wb.x, d[i][j][3] + wb.y);
            *(float2*)&g_xw[r * H_ + col]       = o0;
            *(float2*)&g_xw[(r + 8) * H_ + col] = o1;
        }
    }
}

// ---------------------------------------------------------------------------
// Scan: one CTA per batch, 256 threads. The proven R6 loop, solo (no flags).
// ---------------------------------------------------------------------------
#define UREG 192
#define USM  (H_ - UREG)

#define SCAN_SMEM_FLOATS (USM * H_ + 2 * H_)
#define SMEM_BYTES (SCAN_SMEM_FLOATS * 4)

__global__ __launch_bounds__(256, 1)
void rnn_scan(const float* __restrict__ Ub,
              float* __restrict__ Out,     // [B,S,H]
              float* __restrict__ Tfin) {  // [B,H]
    extern __shared__ float sm[];
    float2* u2  = (float2*)sm;
    float*  vsm = sm + (size_t)USM * H_;

    const int tid = threadIdx.x;
    const int b   = blockIdx.x;

    float uw[UREG];
    #pragma unroll
    for (int j = 0; j < UREG; j++)
        uw[j] = g_UwT[j * H_ + tid];

    for (int r2 = 0; r2 < USM / 2; r2++) {
        float a = g_UwT[(UREG + 2 * r2 + 0) * H_ + tid];
        float c = g_UwT[(UREG + 2 * r2 + 1) * H_ + tid];
        u2[r2 * H_ + tid] = make_float2(a, c);
    }
    __syncthreads();

    const float ub = Ub[tid];
    float t = 0.0f;

    const float* xwp = g_xw + (size_t)b * S_ * H_ + tid;
    float*       op  = Out  + (size_t)b * S_ * H_ + tid;

    float xv = __ldcs(xwp);

    for (int s = 0; s < S_; s++) {
        float v = fast_tanh(xv + t);
        float* vb = vsm + (s & 1) * H_;
        vb[tid] = v;
        __syncthreads();

        if (s + 1 < S_) xv = __ldcs(xwp + (size_t)(s + 1) * H_);

        const float4* v4 = (const float4*)vb;
        float a0 = ub, a1 = 0.f, a2 = 0.f, a3 = 0.f;
        float a4 = 0.f, a5 = 0.f, a6 = 0.f, a7 = 0.f;

        float4 vA = v4[0];
        float4 vB = v4[1];

        // Register section: rows [0,192) = 48 float4 groups, pipelined
        #pragma unroll
        for (int q = 0; q < 48; q += 2) {
            float4 nA = v4[q + 2];
            float4 nB = v4[q + 3];
            const int j = 4 * q;
            a0 += uw[j + 0] * vA.x;  a1 += uw[j + 1] * vA.y;
            a2 += uw[j + 2] * vA.z;  a3 += uw[j + 3] * vA.w;
            a4 += uw[j + 4] * vB.x;  a5 += uw[j + 5] * vB.y;
            a6 += uw[j + 6] * vB.z;  a7 += uw[j + 7] * vB.w;
            vA = nA; vB = nB;
        }

        // Shared-memory section: rows [192,256) = 16 float4 groups
        const float2* up = u2 + tid;
        #pragma unroll
        for (int q = 48; q < 64; q += 2) {
            float4 nA, nB;
            if (q + 2 < 64) { nA = v4[q + 2]; nB = v4[q + 3]; }
            else            { nA = vA;        nB = vB;        }
            const int r2b = (4 * q - UREG) >> 1;
            float2 u0 = up[(r2b + 0) * H_];
            float2 u1 = up[(r2b + 1) * H_];
            float2 uu = up[(r2b + 2) * H_];
            float2 u3 = up[(r2b + 3) * H_];
            a0 += u0.x * vA.x;  a1 += u0.y * vA.y;
            a2 += u1.x * vA.z;  a3 += u1.y * vA.w;
            a4 += uu.x * vB.x;  a5 += uu.y * vB.y;
            a6 += u3.x * vB.z;  a7 += u3.y * vB.w;
            vA = nA; vB = nB;
        }

        t = ((a0 + a1) + (a2 + a3)) + ((a4 + a5) + (a6 + a7));
        __stcs(&op[(size_t)s * H_], t);
    }

    Tfin[b * H_ + tid] = t;
}

// ---------------------------------------------------------------------------
// Launcher (serial: prep -> tensor-core GEMM -> solo scan)
// ---------------------------------------------------------------------------
extern "C" void kernel_launch(void* const* d_in, const int* in_sizes, int n_in,
                              void* d_out, int out_size) {
    const float* x  = (const float*)d_in[0];   // [B,S,E]
    const float* Ww = (const float*)d_in[1];   // [H,E]
    const float* Wb = (const float*)d_in[2];   // [H]
    const float* Uw = (const float*)d_in[3];   // [H,H]
    const float* Ub = (const float*)d_in[4];   // [H]

    float* out  = (float*)d_out;
    float* tfin = out;                          // [B,H]
    float* O    = out + (size_t)B_ * H_;        // [B,S,H]

    cudaFuncSetAttribute(rnn_scan, cudaFuncAttributeMaxDynamicSharedMemorySize,
                         SMEM_BYTES);

    prep_uwt<<<H_, H_>>>(Uw);
    prep_wsplit<<<H_, H_>>>(Ww);
    prep_xsplit<<<2048, 256>>>(x);
    gemm_bf16<<<dim3(H_ / 64, M_TOT / 128), 256>>>(Wb);
    rnn_scan<<<B_, 256, SMEM_BYTES>>>(Ub, O, tfin);
}